// round 4
// baseline (speedup 1.0000x reference)
#include <cuda_runtime.h>
#include <cuda_bf16.h>
#include <math.h>

// B=16384 samples, L=256 latents, H=16 hidden.
// out[b,l] = sigmoid( sum_h W2[l,h]*softplus(y[b,l]*W1[l,h]+b1[l,h]) + b2[l] )
//
// Single fused kernel:
//  prologue: each CTA tabulates per-latent cubic coefficients of g_l(y)
//            directly into shared memory (5 MLP point-evals per thread),
//  main:     one conflict-free LDS.128 + 3 FMA per output, software-pipelined
//            global loads.

#define LATENTS 256
#define HID     16
#define NINT    16
#define Y_LO    (-6.5f)
#define STEP_F  (13.0f / (float)NINT)
#define INVH_F  ((float)NINT / 13.0f)
#define OFF_F   (6.5f * ((float)NINT / 13.0f))   // = 8.0

#define EV_GRID  296
#define EV_BLK   1024
#define TAB_F4   (NINT * LATENTS)                // 4096 float4 = 65536 B

// MLP value + (step-scaled) derivative at one y point, for latent l.
__device__ __forceinline__ void mlp_point(float y0,
                                          const float* __restrict__ W1,
                                          const float* __restrict__ b1,
                                          const float* __restrict__ W2,
                                          float bias2, int l,
                                          float& f, float& m)
{
    float a  = bias2;
    float da = 0.0f;
#pragma unroll
    for (int h = 0; h < HID; ++h) {
        const float w1 = W1[l * HID + h];
        const float bb = b1[l * HID + h];
        const float w2 = W2[l * HID + h];
        const float x  = fmaf(y0, w1, bb);
        const float e  = __expf(-fabsf(x));                  // exp(-|x|) <= 1
        const float iv = __fdividef(1.0f, 1.0f + e);
        const float sp = fmaxf(x, 0.0f) + __logf(1.0f + e);  // softplus(x)
        const float s  = (x >= 0.0f) ? iv : e * iv;          // sigmoid(x)
        a  = fmaf(w2, sp, a);
        da = fmaf(w2 * s, w1, da);
    }
    const float eo = __expf(-a);
    const float g  = __fdividef(1.0f, 1.0f + eo);
    f = g;
    m = STEP_F * (g * (1.0f - g) * da);
}

__device__ __forceinline__ float interp(float yv, const float4* __restrict__ lcol)
{
    float t = fmaf(yv, INVH_F, OFF_F);
    t = fminf(fmaxf(t, 0.0f), (float)NINT - 5e-4f);
    const int   i = (int)t;
    const float u = t - (float)i;
    const float4 c = lcol[i * LATENTS];
    return fmaf(fmaf(fmaf(c.w, u, c.z), u, c.y), u, c.x);
}

__global__ __launch_bounds__(EV_BLK, 2)
void fused_mlp_table_kernel(const float* __restrict__ y,
                            const float* __restrict__ W1,
                            const float* __restrict__ b1,
                            const float* __restrict__ W2,
                            const float* __restrict__ b2,
                            float* __restrict__ out,
                            int total)
{
    extern __shared__ float4 tab[];              // [NINT][LATENTS]

    const int l = threadIdx.x & (LATENTS - 1);

    // ---- prologue: build coefficient table in-place ----
    {
        const int  ivb   = (threadIdx.x >> 8) * 4;     // 0,4,8,12
        const float bias2 = b2[l];

        float f0, m0;
        mlp_point(Y_LO + STEP_F * (float)ivb, W1, b1, W2, bias2, l, f0, m0);
#pragma unroll
        for (int k = 0; k < 4; ++k) {
            float f1, m1;
            mlp_point(Y_LO + STEP_F * (float)(ivb + k + 1),
                      W1, b1, W2, bias2, l, f1, m1);
            float4 c;
            c.x = f0;
            c.y = m0;
            c.z = 3.0f * (f1 - f0) - 2.0f * m0 - m1;
            c.w = 2.0f * (f0 - f1) + m0 + m1;
            tab[(ivb + k) * LATENTS + l] = c;
            f0 = f1; m0 = m1;
        }
    }
    __syncthreads();

    // ---- main loop: pipelined unroll-4 ----
    const int gtid = blockIdx.x * EV_BLK + threadIdx.x;
    const int S    = EV_GRID * EV_BLK;           // multiple of 256
    const float4* lcol = tab + l;                // l == gtid & 255

    int idx = gtid;
    const int last4 = total - 3 * S;

    float a0, a1, a2, a3;
    if (idx < last4) {
        a0 = y[idx];
        a1 = y[idx + S];
        a2 = y[idx + 2 * S];
        a3 = y[idx + 3 * S];
    }
    while (idx < last4) {
        const int nidx = idx + 4 * S;
        float n0, n1, n2, n3;
        if (nidx < last4) {                      // prefetch next batch
            n0 = y[nidx];
            n1 = y[nidx + S];
            n2 = y[nidx + 2 * S];
            n3 = y[nidx + 3 * S];
        }
        out[idx]         = interp(a0, lcol);
        out[idx + S]     = interp(a1, lcol);
        out[idx + 2 * S] = interp(a2, lcol);
        out[idx + 3 * S] = interp(a3, lcol);
        a0 = n0; a1 = n1; a2 = n2; a3 = n3;
        idx = nidx;
    }
    for (; idx < total; idx += S)
        out[idx] = interp(y[idx], lcol);
}

extern "C" void kernel_launch(void* const* d_in, const int* in_sizes, int n_in,
                              void* d_out, int out_size)
{
    // metadata order: t, y, W1, b1, W2, b2, args
    const float* y  = (const float*)d_in[1];
    const float* W1 = (const float*)d_in[2];
    const float* b1 = (const float*)d_in[3];
    const float* W2 = (const float*)d_in[4];
    const float* b2 = (const float*)d_in[5];
    float* out = (float*)d_out;

    const int total = in_sizes[1];               // B*L = 4,194,304

    static int smem_set = 0;
    const int smem_bytes = TAB_F4 * (int)sizeof(float4);   // 65536
    if (!smem_set) {
        cudaFuncSetAttribute(fused_mlp_table_kernel,
                             cudaFuncAttributeMaxDynamicSharedMemorySize,
                             smem_bytes);
        smem_set = 1;
    }

    fused_mlp_table_kernel<<<EV_GRID, EV_BLK, smem_bytes>>>(
        y, W1, b1, W2, b2, out, total);
}

// round 7
// speedup vs baseline: 3.8687x; 3.8687x over previous
#include <cuda_runtime.h>
#include <cuda_bf16.h>
#include <math.h>

// B=16384 samples, L=256 latents, H=16 hidden.
// out[b,l] = sigmoid( sum_h W2[l,h]*softplus(y[b,l]*W1[l,h]+b1[l,h]) + b2[l] )
//
// Kernel 1 (tiny): tabulate {g_l(y_pt), h*g_l'(y_pt)} at 17 grid points.
// Kernel 2: per-CTA assemble per-interval cubic coefficients into swizzled
//           smem, then stream y/out as float4 with conflict-free LDS.128.

#define LATENTS 256
#define HID     16
#define NINT    16
#define NPTS    (NINT + 1)
#define Y_LO    (-6.5f)
#define STEP_F  (13.0f / (float)NINT)
#define INVH_F  ((float)NINT / 13.0f)
#define OFF_F   8.0f                       // -Y_LO * INVH

#define EV_GRID  296
#define EV_BLK   1024
#define TAB_F4   (NINT * LATENTS)          // 4096 float4 = 65536 B

// Point table {f, h*f'} in device global scratch (allocation-free).
__device__ float2 g_pts[NPTS * LATENTS];

// ---------------------------------------------------------------------------
// Build: one thread per (pt, latent). 17 blocks x 256 threads, MUFU intrinsics.
// ---------------------------------------------------------------------------
__global__ void build_pts_kernel(const float* __restrict__ W1,
                                 const float* __restrict__ b1,
                                 const float* __restrict__ W2,
                                 const float* __restrict__ b2)
{
    const int l  = threadIdx.x;            // 0..255
    const int pt = blockIdx.x;             // 0..16
    const float y0 = Y_LO + STEP_F * (float)pt;

    float a  = b2[l];
    float da = 0.0f;
#pragma unroll
    for (int h = 0; h < HID; ++h) {
        const float w1 = W1[l * HID + h];
        const float bb = b1[l * HID + h];
        const float w2 = W2[l * HID + h];
        const float x  = fmaf(y0, w1, bb);
        const float e  = __expf(-fabsf(x));                  // exp(-|x|) <= 1
        const float iv = __fdividef(1.0f, 1.0f + e);
        const float sp = fmaxf(x, 0.0f) + __logf(1.0f + e);  // softplus(x)
        const float s  = (x >= 0.0f) ? iv : e * iv;          // sigmoid(x)
        a  = fmaf(w2, sp, a);
        da = fmaf(w2 * s, w1, da);
    }
    const float eo = __expf(-a);
    const float g  = __fdividef(1.0f, 1.0f + eo);
    g_pts[pt * LATENTS + l] = make_float2(g, STEP_F * (g * (1.0f - g) * da));
}

// ---------------------------------------------------------------------------
// Eval: 296 CTAs x 1024 threads, 64KB smem (2 CTAs/SM).
// Smem layout (swizzled for float4-of-y access):
//   tab[iv * 256 + (l & 3) * 64 + (l >> 2)]
// Thread handles 4 consecutive latents l = 4*lg+j (lg = gtid & 63); for fixed
// j the LDS.128 addresses across lanes are stride-16B -> conflict-free, and
// data-dependent iv contributes multiples of 4096B (bank-invariant).
// ---------------------------------------------------------------------------
__device__ __forceinline__ float interp1(float yv, const float4* __restrict__ col)
{
    float t = fmaf(yv, INVH_F, OFF_F);
    t = fminf(fmaxf(t, 0.0f), (float)NINT - 5e-4f);
    const int   i = (int)t;
    const float u = t - (float)i;
    const float4 c = col[i * LATENTS];     // stride 4096B per interval
    return fmaf(fmaf(fmaf(c.w, u, c.z), u, c.y), u, c.x);
}

__global__ __launch_bounds__(EV_BLK, 2)
void eval_vec_kernel(const float4* __restrict__ y4,
                     float4* __restrict__ out4,
                     int n4)
{
    extern __shared__ float4 tab[];        // [NINT][256] swizzled

    // ---- prologue: assemble coefficients from the point table ----
    // 4096 entries, 1024 threads -> 4 iterations each.
#pragma unroll
    for (int t = threadIdx.x; t < NINT * LATENTS; t += EV_BLK) {
        const int ivp = t >> 8;                    // 0..15
        const int lp  = t & (LATENTS - 1);
        const float2 p0 = g_pts[ivp * LATENTS + lp];
        const float2 p1 = g_pts[(ivp + 1) * LATENTS + lp];
        float4 c;
        c.x = p0.x;
        c.y = p0.y;
        c.z = 3.0f * (p1.x - p0.x) - 2.0f * p0.y - p1.y;
        c.w = 2.0f * (p0.x - p1.x) + p0.y + p1.y;
        tab[ivp * LATENTS + (lp & 3) * 64 + (lp >> 2)] = c;
    }
    __syncthreads();

    const int gtid = blockIdx.x * EV_BLK + threadIdx.x;
    const int S    = EV_GRID * EV_BLK;     // float4 stride; multiple of 64
    const int lg   = gtid & 63;            // latent group (4 latents)

    const float4* c0 = tab + lg;           // j=0 column
    const float4* c1 = tab + lg + 64;      // j=1
    const float4* c2 = tab + lg + 128;     // j=2
    const float4* c3 = tab + lg + 192;     // j=3

    int idx = gtid;
    float4 cur;
    if (idx < n4) cur = y4[idx];
    while (idx < n4) {
        const int nidx = idx + S;
        float4 nxt;
        if (nidx < n4) nxt = y4[nidx];     // prefetch next batch

        float4 r;
        r.x = interp1(cur.x, c0);
        r.y = interp1(cur.y, c1);
        r.z = interp1(cur.z, c2);
        r.w = interp1(cur.w, c3);
        out4[idx] = r;

        cur = nxt;
        idx = nidx;
    }
}

extern "C" void kernel_launch(void* const* d_in, const int* in_sizes, int n_in,
                              void* d_out, int out_size)
{
    // metadata order: t, y, W1, b1, W2, b2, args
    const float* y  = (const float*)d_in[1];
    const float* W1 = (const float*)d_in[2];
    const float* b1 = (const float*)d_in[3];
    const float* W2 = (const float*)d_in[4];
    const float* b2 = (const float*)d_in[5];
    float* out = (float*)d_out;

    const int total = in_sizes[1];         // B*L = 4,194,304 (multiple of 4)
    const int n4 = total / 4;

    static int smem_set = 0;
    const int smem_bytes = TAB_F4 * (int)sizeof(float4);   // 65536
    if (!smem_set) {
        cudaFuncSetAttribute(eval_vec_kernel,
                             cudaFuncAttributeMaxDynamicSharedMemorySize,
                             smem_bytes);
        smem_set = 1;
    }

    build_pts_kernel<<<NPTS, LATENTS>>>(W1, b1, W2, b2);
    eval_vec_kernel<<<EV_GRID, EV_BLK, smem_bytes>>>(
        (const float4*)y, (float4*)out, n4);
}

// round 8
// speedup vs baseline: 4.3283x; 1.1188x over previous
#include <cuda_runtime.h>
#include <cuda_bf16.h>
#include <math.h>

// B=16384 samples, L=256 latents, H=16 hidden.
// out[b,l] = sigmoid( sum_h W2[l,h]*softplus(y[b,l]*W1[l,h]+b1[l,h]) + b2[l] )
//
// Single kernel:
//  phase 1: 4352 MLP point-evals {g, h*g'} spread across all 296 CTAs
//           (task = lane*296 + blockIdx.x), written to global g_pts.
//  barrier: monotonic ticket counter (replay-safe across graph replays).
//  phase 2: per-CTA assemble per-interval cubic coefficients into swizzled
//           smem, then stream y/out as float4 with conflict-free LDS.128.

#define LATENTS 256
#define HID     16
#define NINT    16
#define NPTS    (NINT + 1)
#define Y_LO    (-6.5f)
#define STEP_F  (13.0f / (float)NINT)
#define INVH_F  ((float)NINT / 13.0f)
#define OFF_F   8.0f                       // -Y_LO * INVH

#define EV_GRID  296
#define EV_BLK   1024
#define NTASK    (NPTS * LATENTS)          // 4352 point-evals
#define TAB_F4   (NINT * LATENTS)          // 4096 float4 = 65536 B

// Global scratch (allocation-free).
__device__ float2 g_pts[NTASK];
__device__ unsigned long long g_bar = 0;   // monotonic barrier ticket

// MLP value + step-scaled derivative at grid point pt, latent l.
__device__ __forceinline__ float2 mlp_point(int task,
                                            const float* __restrict__ W1,
                                            const float* __restrict__ b1,
                                            const float* __restrict__ W2,
                                            const float* __restrict__ b2)
{
    const int pt = task >> 8;              // 0..16
    const int l  = task & (LATENTS - 1);
    const float y0 = Y_LO + STEP_F * (float)pt;

    float a  = b2[l];
    float da = 0.0f;
#pragma unroll
    for (int h = 0; h < HID; ++h) {
        const float w1 = W1[l * HID + h];
        const float bb = b1[l * HID + h];
        const float w2 = W2[l * HID + h];
        const float x  = fmaf(y0, w1, bb);
        const float e  = __expf(-fabsf(x));                  // exp(-|x|) <= 1
        const float iv = __fdividef(1.0f, 1.0f + e);
        const float sp = fmaxf(x, 0.0f) + __logf(1.0f + e);  // softplus(x)
        const float s  = (x >= 0.0f) ? iv : e * iv;          // sigmoid(x)
        a  = fmaf(w2, sp, a);
        da = fmaf(w2 * s, w1, da);
    }
    const float eo = __expf(-a);
    const float g  = __fdividef(1.0f, 1.0f + eo);
    return make_float2(g, STEP_F * (g * (1.0f - g) * da));
}

__device__ __forceinline__ float interp1(float yv, const float4* __restrict__ col)
{
    float t = fmaf(yv, INVH_F, OFF_F);
    t = fminf(fmaxf(t, 0.0f), (float)NINT - 5e-4f);
    const int   i = (int)t;
    const float u = t - (float)i;
    const float4 c = col[i * LATENTS];     // stride 4096B per interval
    return fmaf(fmaf(fmaf(c.w, u, c.z), u, c.y), u, c.x);
}

__global__ __launch_bounds__(EV_BLK, 2)
void fused_kernel(const float4* __restrict__ y4,
                  float4* __restrict__ out4,
                  const float* __restrict__ W1,
                  const float* __restrict__ b1,
                  const float* __restrict__ W2,
                  const float* __restrict__ b2,
                  int n4)
{
    extern __shared__ float4 tab[];        // [NINT][256] swizzled

    const int gtid = blockIdx.x * EV_BLK + threadIdx.x;
    const int S    = EV_GRID * EV_BLK;     // float4 stride; multiple of 64

    // ---- prefetch first y batch (independent of the table) ----
    int idx = gtid;
    float4 cur;
    if (idx < n4) cur = y4[idx];

    // ---- phase 1: distributed point-eval build ----
    {
        const int task = threadIdx.x * EV_GRID + blockIdx.x;  // lane-major spread
        if (threadIdx.x < 15 && task < NTASK) {
            g_pts[task] = mlp_point(task, W1, b1, W2, b2);
            __threadfence();               // make the write globally visible
        }
    }
    __syncthreads();

    // ---- device-wide ticket barrier (replay-safe: counter is monotonic) ----
    if (threadIdx.x == 0) {
        const unsigned long long ticket = atomicAdd(&g_bar, 1ULL);
        const unsigned long long target =
            (ticket / (unsigned long long)EV_GRID + 1ULL) * (unsigned long long)EV_GRID;
        while (atomicAdd(&g_bar, 0ULL) < target) { }
    }
    __syncthreads();
    __threadfence();                       // acquire: order g_pts reads after spin

    // ---- phase 2a: assemble coefficients into swizzled smem ----
#pragma unroll
    for (int t = threadIdx.x; t < TAB_F4; t += EV_BLK) {
        const int ivp = t >> 8;                    // 0..15
        const int lp  = t & (LATENTS - 1);
        const float2 p0 = g_pts[ivp * LATENTS + lp];
        const float2 p1 = g_pts[(ivp + 1) * LATENTS + lp];
        float4 c;
        c.x = p0.x;
        c.y = p0.y;
        c.z = 3.0f * (p1.x - p0.x) - 2.0f * p0.y - p1.y;
        c.w = 2.0f * (p0.x - p1.x) + p0.y + p1.y;
        tab[ivp * LATENTS + (lp & 3) * 64 + (lp >> 2)] = c;
    }
    __syncthreads();

    // ---- phase 2b: stream y -> out ----
    // Thread handles latents l = 4*lg+j (lg = gtid & 63); per-j LDS.128 is
    // stride-16B across lanes (conflict-free); iv adds multiples of 4096B.
    const int lg = gtid & 63;
    const float4* c0 = tab + lg;
    const float4* c1 = tab + lg + 64;
    const float4* c2 = tab + lg + 128;
    const float4* c3 = tab + lg + 192;

    while (idx < n4) {
        const int nidx = idx + S;
        float4 nxt;
        if (nidx < n4) nxt = y4[nidx];     // prefetch next batch

        float4 r;
        r.x = interp1(cur.x, c0);
        r.y = interp1(cur.y, c1);
        r.z = interp1(cur.z, c2);
        r.w = interp1(cur.w, c3);
        out4[idx] = r;

        cur = nxt;
        idx = nidx;
    }
}

extern "C" void kernel_launch(void* const* d_in, const int* in_sizes, int n_in,
                              void* d_out, int out_size)
{
    // metadata order: t, y, W1, b1, W2, b2, args
    const float* y  = (const float*)d_in[1];
    const float* W1 = (const float*)d_in[2];
    const float* b1 = (const float*)d_in[3];
    const float* W2 = (const float*)d_in[4];
    const float* b2 = (const float*)d_in[5];
    float* out = (float*)d_out;

    const int total = in_sizes[1];         // B*L = 4,194,304 (multiple of 4)
    const int n4 = total / 4;

    static int smem_set = 0;
    const int smem_bytes = TAB_F4 * (int)sizeof(float4);   // 65536
    if (!smem_set) {
        cudaFuncSetAttribute(fused_kernel,
                             cudaFuncAttributeMaxDynamicSharedMemorySize,
                             smem_bytes);
        smem_set = 1;
    }

    fused_kernel<<<EV_GRID, EV_BLK, smem_bytes>>>(
        (const float4*)y, (float4*)out, W1, b1, W2, b2, n4);
}